// round 14
// baseline (speedup 1.0000x reference)
#include <cuda_runtime.h>
#include <cuda_bf16.h>
#include <cuda_fp16.h>
#include <cstdint>

#define BB 8
#define NN 2048
#define HH 256

// ---------------- device scratch ----------------
__device__ __align__(16) __half       g_x16[BB*NN*HH];
__device__ __align__(16) __half       g_y16[BB*NN*HH];
__device__ __align__(16) __half       g_A16[HH*HH];   // Amat^T [col][dim], fp16
__device__ __align__(16) __nv_bfloat16 g_Wqh[HH*HH];
__device__ __align__(16) __nv_bfloat16 g_Wql[HH*HH];
__device__ __align__(16) __nv_bfloat16 g_Wkh[HH*HH];
__device__ __align__(16) __nv_bfloat16 g_Wkl[HH*HH];
__device__ __align__(16) float g_w[BB*NN];
__device__ __align__(16) float g_t[BB*NN];
__device__ __align__(16) float g_u[HH];
__device__ __align__(16) float g_p[HH];
__device__ float g_c;

// ---------------- helpers ----------------
__device__ __forceinline__ uint32_t smem_u32(const void* p) {
    return (uint32_t)__cvta_generic_to_shared(p);
}
__device__ __forceinline__ void cp16(uint32_t dst, const void* src) {
    asm volatile("cp.async.cg.shared.global [%0], [%1], 16;" :: "r"(dst), "l"(src));
}
__device__ __forceinline__ void cp_commit() { asm volatile("cp.async.commit_group;"); }
template <int N> __device__ __forceinline__ void cp_wait() {
    asm volatile("cp.async.wait_group %0;" :: "n"(N) : "memory");
}
__device__ __forceinline__ void ldsm4(uint32_t* d, uint32_t addr) {
    asm volatile("ldmatrix.sync.aligned.m8n8.x4.shared.b16 {%0,%1,%2,%3}, [%4];"
        : "=r"(d[0]), "=r"(d[1]), "=r"(d[2]), "=r"(d[3]) : "r"(addr));
}
__device__ __forceinline__ void mma16816(float* c, const uint32_t* a,
                                         uint32_t b0, uint32_t b1) {
    asm volatile("mma.sync.aligned.m16n8k16.row.col.f32.bf16.bf16.f32 "
        "{%0,%1,%2,%3}, {%4,%5,%6,%7}, {%8,%9}, {%0,%1,%2,%3};"
        : "+f"(c[0]), "+f"(c[1]), "+f"(c[2]), "+f"(c[3])
        : "r"(a[0]), "r"(a[1]), "r"(a[2]), "r"(a[3]), "r"(b0), "r"(b1));
}
__device__ __forceinline__ void mma16816h(float* c, const uint32_t* a,
                                          uint32_t b0, uint32_t b1) {
    asm volatile("mma.sync.aligned.m16n8k16.row.col.f32.f16.f16.f32 "
        "{%0,%1,%2,%3}, {%4,%5,%6,%7}, {%8,%9}, {%0,%1,%2,%3};"
        : "+f"(c[0]), "+f"(c[1]), "+f"(c[2]), "+f"(c[3])
        : "r"(a[0]), "r"(a[1]), "r"(a[2]), "r"(a[3]), "r"(b0), "r"(b1));
}
#define SW128(o) ((o) ^ (((o) >> 3) & 0x70))
__device__ __forceinline__ uint32_t pack_h(float a, float b) {
    __half2 h = __floats2half2_rn(a, b);
    return *(uint32_t*)&h;
}
__device__ __forceinline__ void split2(float v, __nv_bfloat16& h, __nv_bfloat16& l) {
    h = __float2bfloat16(v);
    l = __float2bfloat16(v - __bfloat162float(h));
}

// Stage a 32-row x 256-dim bf16 hi/lo tile (SW128, 64-dim blocks). 256 threads.
__device__ __forceinline__ void stage32(uint32_t dst, const __nv_bfloat16* ph,
                                        const __nv_bfloat16* pl, int tid) {
    #pragma unroll
    for (int i = 0; i < 4; i++) {
        int idx = tid + i * 256, r = idx >> 5, d = (idx & 31) * 8;
        uint32_t off = (uint32_t)(d >> 6) * 4096u + SW128((uint32_t)(r * 128 + (d & 63) * 2));
        cp16(dst + off, ph + (size_t)r * HH + d);
        cp16(dst + 16384u + off, pl + (size_t)r * HH + d);
    }
}
// 128-row bf16 hi/lo A tile, 256 threads (64-dim blocks stride 16384).
__device__ __forceinline__ void stageA2(uint32_t hbase, uint32_t lbase,
                                        const __nv_bfloat16* ph, const __nv_bfloat16* pl,
                                        int tid) {
    #pragma unroll
    for (int i = 0; i < 16; i++) {
        int idx = tid + i * 256, r = idx >> 5, d = (idx & 31) * 8;
        uint32_t off = (uint32_t)(d >> 6) * 16384u + SW128((uint32_t)(r * 128 + (d & 63) * 2));
        cp16(hbase + off, ph + (size_t)r * HH + d);
        cp16(lbase + off, pl + (size_t)r * HH + d);
    }
}
// 128-row x 256-dim fp16 tile at dst (64 KB, blocks stride 16384). 256 threads.
__device__ __forceinline__ void stageY16(uint32_t dst, const __half* p, int tid) {
    #pragma unroll
    for (int i = 0; i < 16; i++) {
        int idx = tid + i * 256, r = idx >> 5, d = (idx & 31) * 8;
        uint32_t off = (uint32_t)(d >> 6) * 16384u + SW128((uint32_t)(r * 128 + (d & 63) * 2));
        cp16(dst + off, p + (size_t)r * HH + d);
    }
}
// 128-row x 256-dim fp16 tile at dst, 128 threads.
__device__ __forceinline__ void stageY16_128(uint32_t dst, const __half* p, int tid) {
    #pragma unroll
    for (int i = 0; i < 32; i++) {
        int idx = tid + i * 128, r = idx >> 5, d = (idx & 31) * 8;
        uint32_t off = (uint32_t)(d >> 6) * 16384u + SW128((uint32_t)(r * 128 + (d & 63) * 2));
        cp16(dst + off, p + (size_t)r * HH + d);
    }
}
// 64-row x 256-dim fp16 tile at dst (32 KB, blocks stride 8192). 256 threads.
__device__ __forceinline__ void stage64h(uint32_t dst, const __half* p, int tid) {
    #pragma unroll
    for (int i = 0; i < 8; i++) {
        int idx = tid + i * 256, r = idx >> 5, d = (idx & 31) * 8;
        uint32_t off = (uint32_t)(d >> 6) * 8192u + SW128((uint32_t)(r * 128 + (d & 63) * 2));
        cp16(dst + off, p + (size_t)r * HH + d);
    }
}
// 64-row x 256-dim fp16 tile, 128 threads.
__device__ __forceinline__ void stage64h_128(uint32_t dst, const __half* p, int tid) {
    #pragma unroll
    for (int i = 0; i < 16; i++) {
        int idx = tid + i * 128, r = idx >> 5, d = (idx & 31) * 8;
        uint32_t off = (uint32_t)(d >> 6) * 8192u + SW128((uint32_t)(r * 128 + (d & 63) * 2));
        cp16(dst + off, p + (size_t)r * HH + d);
    }
}
// Preload A fragments: 16 kk-steps x 4 regs (blocks stride 16384).
__device__ __forceinline__ void preloadA(uint32_t hbase, uint32_t sq, uint32_t ahr[16][4]) {
    #pragma unroll
    for (int kk = 0; kk < 16; kk++) {
        uint32_t cx = (uint32_t)(kk & 3) * 32u;
        uint32_t bq = (uint32_t)(kk >> 2) * 16384u;
        ldsm4(ahr[kk], hbase + bq + (sq ^ cx));
    }
}

// 128x32x256 bf16 3-pass score block (Amat path, R6-proven).
__device__ __forceinline__ void score32(uint32_t albase, uint32_t kbuf,
                                        const uint32_t ahr[16][4], uint32_t sq,
                                        uint32_t sk0, uint32_t sk1, float a4[4][4]) {
    #pragma unroll
    for (int kk = 0; kk < 16; kk++) {
        const uint32_t cx = (uint32_t)(kk & 3) * 32u;
        const uint32_t bq = (uint32_t)(kk >> 2) * 16384u;
        const uint32_t bk = (uint32_t)(kk >> 2) * 4096u;
        uint32_t al[4], b0h[4], b1h[4], b0l[4], b1l[4];
        ldsm4(al, albase + bq + (sq ^ cx));
        ldsm4(b0h, kbuf + bk + (sk0 ^ cx));
        ldsm4(b1h, kbuf + bk + (sk1 ^ cx));
        ldsm4(b0l, kbuf + 16384u + bk + (sk0 ^ cx));
        ldsm4(b1l, kbuf + 16384u + bk + (sk1 ^ cx));
        const uint32_t* ah = ahr[kk];
        mma16816(a4[0], ah, b0h[0], b0h[1]);
        mma16816(a4[1], ah, b0h[2], b0h[3]);
        mma16816(a4[2], ah, b1h[0], b1h[1]);
        mma16816(a4[3], ah, b1h[2], b1h[3]);
        mma16816(a4[0], ah, b0l[0], b0l[1]);
        mma16816(a4[1], ah, b0l[2], b0l[3]);
        mma16816(a4[2], ah, b1l[0], b1l[1]);
        mma16816(a4[3], ah, b1l[2], b1l[3]);
        mma16816(a4[0], al, b0h[0], b0h[1]);
        mma16816(a4[1], al, b0h[2], b0h[3]);
        mma16816(a4[2], al, b1h[0], b1h[1]);
        mma16816(a4[3], al, b1h[2], b1h[3]);
    }
}

// 128x64x256 fp16 single-pass score block (R11-proven, y16 path).
__device__ __forceinline__ void score64h(uint32_t kbuf, const uint32_t ahr[16][4],
                                         uint32_t sk0, float a4[8][4]) {
    #pragma unroll
    for (int kk = 0; kk < 16; kk++) {
        const uint32_t cx = (uint32_t)(kk & 3) * 32u;
        const uint32_t bk = (uint32_t)(kk >> 2) * 8192u;
        uint32_t bh[4][4];
        #pragma unroll
        for (int t = 0; t < 4; t++)
            ldsm4(bh[t], kbuf + bk + ((sk0 + (uint32_t)t * 2048u) ^ cx));
        const uint32_t* ah = ahr[kk];
        #pragma unroll
        for (int t = 0; t < 4; t++) {
            mma16816h(a4[2 * t], ah, bh[t][0], bh[t][1]);
            mma16816h(a4[2 * t + 1], ah, bh[t][2], bh[t][3]);
        }
    }
}

// 32q x 64k x 256 fp16 score block, dual A-chunks: chunk0 from regs, chunk1
// LDSM'd from the persistent Y region (blocks stride 16384). B at kbuf
// (64-row layout, blocks stride 8192). B fragments reused by both chunks.
__device__ __forceinline__ void score64h2(uint32_t ybase, uint32_t kbuf,
                                          const uint32_t ahr[16][4], uint32_t sq1,
                                          uint32_t sk0, float a0[8][4], float a1[8][4]) {
    #pragma unroll
    for (int kk = 0; kk < 16; kk++) {
        const uint32_t cx = (uint32_t)(kk & 3) * 32u;
        const uint32_t bkB = (uint32_t)(kk >> 2) * 8192u;
        const uint32_t bqY = (uint32_t)(kk >> 2) * 16384u;
        uint32_t a1f[4], bh[4][4];
        ldsm4(a1f, ybase + bqY + (sq1 ^ cx));
        #pragma unroll
        for (int t = 0; t < 4; t++)
            ldsm4(bh[t], kbuf + bkB + ((sk0 + (uint32_t)t * 2048u) ^ cx));
        const uint32_t* ah = ahr[kk];
        #pragma unroll
        for (int t = 0; t < 4; t++) {
            mma16816h(a0[2 * t], ah, bh[t][0], bh[t][1]);
            mma16816h(a0[2 * t + 1], ah, bh[t][2], bh[t][3]);
        }
        #pragma unroll
        for (int t = 0; t < 4; t++) {
            mma16816h(a1[2 * t], a1f, bh[t][0], bh[t][1]);
            mma16816h(a1[2 * t + 1], a1f, bh[t][2], bh[t][3]);
        }
    }
}

// ---------------- kernel 0: u = Wv@Ww, p = (Wk@bq)/16, c = bv.Ww ----------------
__global__ void prep_kernel(const float* __restrict__ Wv, const float* __restrict__ Ww,
                            const float* __restrict__ bv, const float* __restrict__ Wk,
                            const float* __restrict__ bq) {
    int warp = threadIdx.x >> 5, lane = threadIdx.x & 31;
    for (int row = warp; row < HH; row += 8) {
        float su = 0.f, sp = 0.f;
        #pragma unroll
        for (int m = 0; m < 8; m++) {
            su += Wv[row * HH + m * 32 + lane] * Ww[m * 32 + lane];
            sp += Wk[row * HH + m * 32 + lane] * bq[m * 32 + lane];
        }
        for (int o = 16; o; o >>= 1) {
            su += __shfl_down_sync(0xffffffffu, su, o);
            sp += __shfl_down_sync(0xffffffffu, sp, o);
        }
        if (!lane) { g_u[row] = su; g_p[row] = sp * 0.0625f; }
    }
    if (threadIdx.x == 0) {
        float c = 0.f;
        for (int j = 0; j < HH; j++) c += bv[j] * Ww[j];
        g_c = c;
    }
}

// ---------------- kernel 1: plain bf16 hi/lo splits of Wq, Wk ----------------
__global__ void prep_w2_kernel(const float* __restrict__ Wq, const float* __restrict__ Wk) {
    int j = blockIdx.y, d = threadIdx.x;
    const float* W = blockIdx.x ? Wk : Wq;
    __nv_bfloat16* oh = blockIdx.x ? g_Wkh : g_Wqh;
    __nv_bfloat16* ol = blockIdx.x ? g_Wkl : g_Wql;
    __nv_bfloat16 hi, lo;
    split2(W[j * HH + d], hi, lo);
    oh[j * HH + d] = hi;
    ol[j * HH + d] = lo;
}

// ---------------- kernel 2: x -> fp16 + w = x.u + c, t = x.p ----------------
__global__ void xw_kernel(const float* __restrict__ x) {
    int warp = threadIdx.x >> 5, lane = threadIdx.x & 31;
    int row = blockIdx.x * 8 + warp;
    const float* xr = x + (size_t)row * HH + lane * 8;
    const float* up = g_u + lane * 8;
    const float* pp = g_p + lane * 8;
    uint32_t h16[4];
    float s = 0.f, s2 = 0.f;
    #pragma unroll
    for (int g = 0; g < 2; g++) {
        float4 v = *(const float4*)(xr + g * 4);
        h16[g * 2] = pack_h(v.x, v.y); h16[g * 2 + 1] = pack_h(v.z, v.w);
        s  += v.x * up[g * 4] + v.y * up[g * 4 + 1] + v.z * up[g * 4 + 2] + v.w * up[g * 4 + 3];
        s2 += v.x * pp[g * 4] + v.y * pp[g * 4 + 1] + v.z * pp[g * 4 + 2] + v.w * pp[g * 4 + 3];
    }
    *(uint4*)(g_x16 + (size_t)row * HH + lane * 8) = *(uint4*)h16;
    for (int o = 16; o; o >>= 1) {
        s += __shfl_down_sync(0xffffffffu, s, o);
        s2 += __shfl_down_sync(0xffffffffu, s2, o);
    }
    if (!lane) { g_w[row] = s + g_c; g_t[row] = s2; }
}

// ---------------- kernel 3: Amat = (WqWk^T)^T/16 -> fp16 (3-pass bf16 compute) ----------------
#define AM_SMEM 163840
__global__ __launch_bounds__(256, 1) void amat_mma() {
    extern __shared__ __align__(1024) char sm[];
    const uint32_t smb = smem_u32(sm);
    const int tid = threadIdx.x, warp = tid >> 5, lane = tid & 31;
    const int m0 = blockIdx.x * 128;
    const int cb = blockIdx.y * 32;

    stageA2(smb, smb + 65536u, g_Wkh + (size_t)m0 * HH, g_Wkl + (size_t)m0 * HH, tid);
    cp_commit();
    stage32(smb + 131072u, g_Wqh + (size_t)cb * HH, g_Wql + (size_t)cb * HH, tid);
    cp_commit();

    uint32_t qrowb = (uint32_t)((warp * 16 + (lane & 15)) * 128 + (lane >> 4) * 16);
    uint32_t sq = qrowb ^ ((qrowb >> 3) & 0x70);
    uint32_t kr0 = (uint32_t)((((lane & 7) + ((lane >> 4) << 3))) * 128 + ((lane & 8) << 1));
    uint32_t sk0 = kr0 ^ ((kr0 >> 3) & 0x70);
    uint32_t sk1 = sk0 + 2048u;

    cp_wait<0>(); __syncthreads();
    uint32_t ahr[16][4];
    preloadA(smb, sq, ahr);

    float acc[4][4];
    #pragma unroll
    for (int a = 0; a < 4; a++)
        #pragma unroll
        for (int b2 = 0; b2 < 4; b2++) acc[a][b2] = 0.f;
    score32(smb + 65536u, smb + 131072u, ahr, sq, sk0, sk1, acc);

    const int r0 = m0 + warp * 16 + (lane >> 2);
    #pragma unroll
    for (int nt = 0; nt < 4; nt++) {
        int col = cb + nt * 8 + (lane & 3) * 2;
        *(uint32_t*)(g_A16 + (size_t)r0 * HH + col) =
            pack_h(acc[nt][0] * 0.0625f, acc[nt][1] * 0.0625f);
        *(uint32_t*)(g_A16 + (size_t)(r0 + 8) * HH + col) =
            pack_h(acc[nt][2] * 0.0625f, acc[nt][3] * 0.0625f);
    }
}

// ---------------- kernel 4: y = x * Amat (fp16 single-pass, R13-proven) ----------------
#define Y16_SMEM 65536
__global__ __launch_bounds__(256, 1) void y16_mma() {
    extern __shared__ __align__(1024) char sm[];
    const uint32_t smb = smem_u32(sm);
    const int tid = threadIdx.x, warp = tid >> 5, lane = tid & 31;
    const int m0 = blockIdx.x * 128;

    stageY16(smb, g_x16 + (size_t)m0 * HH, tid);
    cp_commit();

    uint32_t qrowb = (uint32_t)((warp * 16 + (lane & 15)) * 128 + (lane >> 4) * 16);
    uint32_t sq = qrowb ^ ((qrowb >> 3) & 0x70);
    uint32_t kr0 = (uint32_t)((((lane & 7) + ((lane >> 4) << 3))) * 128 + ((lane & 8) << 1));
    uint32_t sk0 = kr0 ^ ((kr0 >> 3) & 0x70);

    cp_wait<0>(); __syncthreads();
    uint32_t ahr[16][4];
    preloadA(smb, sq, ahr);
    __syncthreads();   // preloads done before x area becomes B buffers

    #pragma unroll
    for (int j0 = 0; j0 < 2; j0++) {
        stage64h(smb + (uint32_t)j0 * 32768u, g_A16 + (size_t)j0 * 64 * HH, tid);
        cp_commit();
    }

    const int r0 = m0 + warp * 16 + (lane >> 2);
    for (int j = 0; j < 4; j++) {
        if (j < 3) { cp_wait<1>(); } else { cp_wait<0>(); }
        __syncthreads();
        float acc[8][4];
        #pragma unroll
        for (int a = 0; a < 8; a++)
            #pragma unroll
            for (int b2 = 0; b2 < 4; b2++) acc[a][b2] = 0.f;
        score64h(smb + (uint32_t)(j & 1) * 32768u, ahr, sk0, acc);
        __syncthreads();
        if (j + 2 < 4) {
            stage64h(smb + (uint32_t)(j & 1) * 32768u, g_A16 + (size_t)(j + 2) * 64 * HH, tid);
            cp_commit();
        }
        #pragma unroll
        for (int nt = 0; nt < 8; nt++) {
            int col = j * 64 + nt * 8 + (lane & 3) * 2;
            *(uint32_t*)(g_y16 + (size_t)r0 * HH + col) = pack_h(acc[nt][0], acc[nt][1]);
            *(uint32_t*)(g_y16 + (size_t)(r0 + 8) * HH + col) = pack_h(acc[nt][2], acc[nt][3]);
        }
    }
}

// ---------------- kernel 5: fused attention (4 warps, 32 q-rows/warp) ----------------
// smem: [0,64K) Y16 persistent | [64K,128K) two 32K B buffers | ring @131072: 4x512B.
#define AT2_SMEM 133120
#define BOFF2 65536u
#define RING2 131072u
__global__ __launch_bounds__(128, 1) void attn_f16b(const float* __restrict__ bw,
                                                    float* __restrict__ out) {
    extern __shared__ __align__(1024) char sm[];
    const uint32_t smb = smem_u32(sm);
    const int tid = threadIdx.x, warp = tid >> 5, lane = tid & 31;
    const int b = blockIdx.y, n0 = blockIdx.x * 128;

    const __half* xp = g_x16 + (size_t)b * NN * HH;
    const float* wsrc = g_w + b * NN;
    const float* tsrc = g_t + b * NN;

    stageY16_128(smb, g_y16 + (size_t)(b * NN + n0) * HH, tid);
    cp_commit();

    const int row0 = warp * 32 + (lane & 15);
    uint32_t q0b = (uint32_t)(row0 * 128 + (lane >> 4) * 16);
    uint32_t sq0 = q0b ^ ((q0b >> 3) & 0x70);
    uint32_t q1b = (uint32_t)((row0 + 16) * 128 + (lane >> 4) * 16);
    uint32_t sq1 = q1b ^ ((q1b >> 3) & 0x70);
    uint32_t kr0 = (uint32_t)((((lane & 7) + ((lane >> 4) << 3))) * 128 + ((lane & 8) << 1));
    uint32_t sk0 = kr0 ^ ((kr0 >> 3) & 0x70);

    cp_wait<0>(); __syncthreads();
    uint32_t ahr[16][4];
    preloadA(smb, sq0, ahr);   // chunk0 rows in regs; chunk1 stays in smem

    #pragma unroll
    for (int j0 = 0; j0 < 2; j0++) {
        stage64h_128(smb + BOFF2 + (uint32_t)j0 * 32768u, xp + (size_t)j0 * 64 * HH, tid);
        if (tid < 16) cp16(smb + RING2 + (uint32_t)j0 * 512u + tid * 16u,
                           wsrc + j0 * 64 + tid * 4);
        else if (tid < 32) cp16(smb + RING2 + (uint32_t)j0 * 512u + 256u + (tid - 16) * 16u,
                                tsrc + j0 * 64 + (tid - 16) * 4);
        cp_commit();
    }

    float n00 = 0.f, d00 = 0.f, n01 = 0.f, d01 = 0.f;
    float n10 = 0.f, d10 = 0.f, n11 = 0.f, d11 = 0.f;
    for (int j = 0; j < 32; j++) {
        if (j < 31) { cp_wait<1>(); } else { cp_wait<0>(); }
        __syncthreads();
        float a0[8][4], a1[8][4];
        #pragma unroll
        for (int a = 0; a < 8; a++)
            #pragma unroll
            for (int b2 = 0; b2 < 4; b2++) { a0[a][b2] = 0.f; a1[a][b2] = 0.f; }
        score64h2(smb, smb + BOFF2 + (uint32_t)(j & 1) * 32768u, ahr, sq1, sk0, a0, a1);
        __syncthreads();
        if (j + 2 < 32) {
            stage64h_128(smb + BOFF2 + (uint32_t)(j & 1) * 32768u,
                         xp + (size_t)(j + 2) * 64 * HH, tid);
            if (tid < 16) cp16(smb + RING2 + (uint32_t)((j + 2) & 3) * 512u + tid * 16u,
                               wsrc + (j + 2) * 64 + tid * 4);
            else if (tid < 32) cp16(smb + RING2 + (uint32_t)((j + 2) & 3) * 512u + 256u +
                                        (tid - 16) * 16u,
                                    tsrc + (j + 2) * 64 + (tid - 16) * 4);
            cp_commit();
        }
        const float* wsp = (const float*)(sm + RING2 + (j & 3) * 512);
        const float* tsp = wsp + 64;
        #pragma unroll
        for (int nt = 0; nt < 8; nt++) {
            float2 wv = *(const float2*)(wsp + nt * 8 + (lane & 3) * 2);
            float2 tv = *(const float2*)(tsp + nt * 8 + (lane & 3) * 2);
            float e;
            e = __expf(a0[nt][0] + tv.x); d00 += e; n00 += e * wv.x;
            e = __expf(a0[nt][1] + tv.y); d00 += e; n00 += e * wv.y;
            e = __expf(a0[nt][2] + tv.x); d01 += e; n01 += e * wv.x;
            e = __expf(a0[nt][3] + tv.y); d01 += e; n01 += e * wv.y;
            e = __expf(a1[nt][0] + tv.x); d10 += e; n10 += e * wv.x;
            e = __expf(a1[nt][1] + tv.y); d10 += e; n10 += e * wv.y;
            e = __expf(a1[nt][2] + tv.x); d11 += e; n11 += e * wv.x;
            e = __expf(a1[nt][3] + tv.y); d11 += e; n11 += e * wv.y;
        }
    }
    #pragma unroll
    for (int o = 1; o <= 2; o <<= 1) {
        n00 += __shfl_xor_sync(0xffffffffu, n00, o);
        d00 += __shfl_xor_sync(0xffffffffu, d00, o);
        n01 += __shfl_xor_sync(0xffffffffu, n01, o);
        d01 += __shfl_xor_sync(0xffffffffu, d01, o);
        n10 += __shfl_xor_sync(0xffffffffu, n10, o);
        d10 += __shfl_xor_sync(0xffffffffu, d10, o);
        n11 += __shfl_xor_sync(0xffffffffu, n11, o);
        d11 += __shfl_xor_sync(0xffffffffu, d11, o);
    }
    if (!(lane & 3)) {
        int r = n0 + warp * 32 + (lane >> 2);
        float bwv = __ldg(bw);
        out[b * NN + r] = n00 / d00 + bwv;
        out[b * NN + r + 8] = n01 / d01 + bwv;
        out[b * NN + r + 16] = n10 / d10 + bwv;
        out[b * NN + r + 24] = n11 / d11 + bwv;
    }
}

// ---------------- launch ----------------
extern "C" void kernel_launch(void* const* d_in, const int* in_sizes, int n_in,
                              void* d_out, int out_size) {
    const float* x  = (const float*)d_in[0];
    const float* Wq = (const float*)d_in[1];
    const float* bq = (const float*)d_in[2];
    const float* Wk = (const float*)d_in[3];
    const float* bk = (const float*)d_in[4];
    const float* Wv = (const float*)d_in[5];
    const float* bv = (const float*)d_in[6];
    const float* Ww = (const float*)d_in[7];
    const float* bw = (const float*)d_in[8];
    float* out = (float*)d_out;
    (void)bk;

    cudaFuncSetAttribute(amat_mma, cudaFuncAttributeMaxDynamicSharedMemorySize, AM_SMEM);
    cudaFuncSetAttribute(y16_mma, cudaFuncAttributeMaxDynamicSharedMemorySize, Y16_SMEM);
    cudaFuncSetAttribute(attn_f16b, cudaFuncAttributeMaxDynamicSharedMemorySize, AT2_SMEM);

    prep_kernel<<<1, 256>>>(Wv, Ww, bv, Wk, bq);
    prep_w2_kernel<<<dim3(2, 256), 256>>>(Wq, Wk);
    amat_mma<<<dim3(2, 8), 256, AM_SMEM>>>();        // Amat -> fp16
    xw_kernel<<<BB * NN / 8, 256>>>(x);              // x16, w, t
    y16_mma<<<128, 256, Y16_SMEM>>>();               // y = x * Amat (fp16)
    attn_f16b<<<dim3(16, 8), 128, AT2_SMEM>>>(bw, out);
}

// round 15
// speedup vs baseline: 1.0252x; 1.0252x over previous
#include <cuda_runtime.h>
#include <cuda_bf16.h>
#include <cuda_fp16.h>
#include <cstdint>

#define BB 8
#define NN 2048
#define HH 256

// ---------------- device scratch ----------------
__device__ __align__(16) __half       g_x16[BB*NN*HH];
__device__ __align__(16) __half       g_y16[BB*NN*HH];
__device__ __align__(16) __half       g_A16[HH*HH];   // Amat^T [col][dim], fp16
__device__ __align__(16) __nv_bfloat16 g_Wqh[HH*HH];
__device__ __align__(16) __nv_bfloat16 g_Wql[HH*HH];
__device__ __align__(16) __nv_bfloat16 g_Wkh[HH*HH];
__device__ __align__(16) __nv_bfloat16 g_Wkl[HH*HH];
__device__ __align__(16) float g_w[BB*NN];
__device__ __align__(16) float g_t[BB*NN];
__device__ __align__(16) float g_u[HH];
__device__ __align__(16) float g_p[HH];
__device__ float g_c;

// ---------------- helpers ----------------
__device__ __forceinline__ uint32_t smem_u32(const void* p) {
    return (uint32_t)__cvta_generic_to_shared(p);
}
__device__ __forceinline__ void cp16(uint32_t dst, const void* src) {
    asm volatile("cp.async.cg.shared.global [%0], [%1], 16;" :: "r"(dst), "l"(src));
}
__device__ __forceinline__ void cp_commit() { asm volatile("cp.async.commit_group;"); }
template <int N> __device__ __forceinline__ void cp_wait() {
    asm volatile("cp.async.wait_group %0;" :: "n"(N) : "memory");
}
__device__ __forceinline__ void ldsm4(uint32_t* d, uint32_t addr) {
    asm volatile("ldmatrix.sync.aligned.m8n8.x4.shared.b16 {%0,%1,%2,%3}, [%4];"
        : "=r"(d[0]), "=r"(d[1]), "=r"(d[2]), "=r"(d[3]) : "r"(addr));
}
__device__ __forceinline__ void mma16816(float* c, const uint32_t* a,
                                         uint32_t b0, uint32_t b1) {
    asm volatile("mma.sync.aligned.m16n8k16.row.col.f32.bf16.bf16.f32 "
        "{%0,%1,%2,%3}, {%4,%5,%6,%7}, {%8,%9}, {%0,%1,%2,%3};"
        : "+f"(c[0]), "+f"(c[1]), "+f"(c[2]), "+f"(c[3])
        : "r"(a[0]), "r"(a[1]), "r"(a[2]), "r"(a[3]), "r"(b0), "r"(b1));
}
__device__ __forceinline__ void mma16816h(float* c, const uint32_t* a,
                                          uint32_t b0, uint32_t b1) {
    asm volatile("mma.sync.aligned.m16n8k16.row.col.f32.f16.f16.f32 "
        "{%0,%1,%2,%3}, {%4,%5,%6,%7}, {%8,%9}, {%0,%1,%2,%3};"
        : "+f"(c[0]), "+f"(c[1]), "+f"(c[2]), "+f"(c[3])
        : "r"(a[0]), "r"(a[1]), "r"(a[2]), "r"(a[3]), "r"(b0), "r"(b1));
}
#define SW128(o) ((o) ^ (((o) >> 3) & 0x70))
__device__ __forceinline__ uint32_t pack_h(float a, float b) {
    __half2 h = __floats2half2_rn(a, b);
    return *(uint32_t*)&h;
}
__device__ __forceinline__ void split2(float v, __nv_bfloat16& h, __nv_bfloat16& l) {
    h = __float2bfloat16(v);
    l = __float2bfloat16(v - __bfloat162float(h));
}

// Stage a 32-row x 256-dim bf16 hi/lo tile (SW128, 64-dim blocks). 256 threads.
__device__ __forceinline__ void stage32(uint32_t dst, const __nv_bfloat16* ph,
                                        const __nv_bfloat16* pl, int tid) {
    #pragma unroll
    for (int i = 0; i < 4; i++) {
        int idx = tid + i * 256, r = idx >> 5, d = (idx & 31) * 8;
        uint32_t off = (uint32_t)(d >> 6) * 4096u + SW128((uint32_t)(r * 128 + (d & 63) * 2));
        cp16(dst + off, ph + (size_t)r * HH + d);
        cp16(dst + 16384u + off, pl + (size_t)r * HH + d);
    }
}
// 128-row bf16 hi/lo A tile, 256 threads (64-dim blocks stride 16384).
__device__ __forceinline__ void stageA2(uint32_t hbase, uint32_t lbase,
                                        const __nv_bfloat16* ph, const __nv_bfloat16* pl,
                                        int tid) {
    #pragma unroll
    for (int i = 0; i < 16; i++) {
        int idx = tid + i * 256, r = idx >> 5, d = (idx & 31) * 8;
        uint32_t off = (uint32_t)(d >> 6) * 16384u + SW128((uint32_t)(r * 128 + (d & 63) * 2));
        cp16(hbase + off, ph + (size_t)r * HH + d);
        cp16(lbase + off, pl + (size_t)r * HH + d);
    }
}
// 128-row x 256-dim fp16 tile at dst (64 KB, blocks stride 16384). 256 threads.
__device__ __forceinline__ void stageY16(uint32_t dst, const __half* p, int tid) {
    #pragma unroll
    for (int i = 0; i < 16; i++) {
        int idx = tid + i * 256, r = idx >> 5, d = (idx & 31) * 8;
        uint32_t off = (uint32_t)(d >> 6) * 16384u + SW128((uint32_t)(r * 128 + (d & 63) * 2));
        cp16(dst + off, p + (size_t)r * HH + d);
    }
}
// 64-row x 256-dim fp16 tile at dst (32 KB, blocks stride 8192). 256 threads.
__device__ __forceinline__ void stage64h(uint32_t dst, const __half* p, int tid) {
    #pragma unroll
    for (int i = 0; i < 8; i++) {
        int idx = tid + i * 256, r = idx >> 5, d = (idx & 31) * 8;
        uint32_t off = (uint32_t)(d >> 6) * 8192u + SW128((uint32_t)(r * 128 + (d & 63) * 2));
        cp16(dst + off, p + (size_t)r * HH + d);
    }
}
// Preload A fragments: 16 kk-steps x 4 regs (blocks stride 16384).
__device__ __forceinline__ void preloadA(uint32_t hbase, uint32_t sq, uint32_t ahr[16][4]) {
    #pragma unroll
    for (int kk = 0; kk < 16; kk++) {
        uint32_t cx = (uint32_t)(kk & 3) * 32u;
        uint32_t bq = (uint32_t)(kk >> 2) * 16384u;
        ldsm4(ahr[kk], hbase + bq + (sq ^ cx));
    }
}

// 128x32x256 bf16 3-pass score block (Amat path, R6-proven).
__device__ __forceinline__ void score32(uint32_t albase, uint32_t kbuf,
                                        const uint32_t ahr[16][4], uint32_t sq,
                                        uint32_t sk0, uint32_t sk1, float a4[4][4]) {
    #pragma unroll
    for (int kk = 0; kk < 16; kk++) {
        const uint32_t cx = (uint32_t)(kk & 3) * 32u;
        const uint32_t bq = (uint32_t)(kk >> 2) * 16384u;
        const uint32_t bk = (uint32_t)(kk >> 2) * 4096u;
        uint32_t al[4], b0h[4], b1h[4], b0l[4], b1l[4];
        ldsm4(al, albase + bq + (sq ^ cx));
        ldsm4(b0h, kbuf + bk + (sk0 ^ cx));
        ldsm4(b1h, kbuf + bk + (sk1 ^ cx));
        ldsm4(b0l, kbuf + 16384u + bk + (sk0 ^ cx));
        ldsm4(b1l, kbuf + 16384u + bk + (sk1 ^ cx));
        const uint32_t* ah = ahr[kk];
        mma16816(a4[0], ah, b0h[0], b0h[1]);
        mma16816(a4[1], ah, b0h[2], b0h[3]);
        mma16816(a4[2], ah, b1h[0], b1h[1]);
        mma16816(a4[3], ah, b1h[2], b1h[3]);
        mma16816(a4[0], ah, b0l[0], b0l[1]);
        mma16816(a4[1], ah, b0l[2], b0l[3]);
        mma16816(a4[2], ah, b1l[0], b1l[1]);
        mma16816(a4[3], ah, b1l[2], b1l[3]);
        mma16816(a4[0], al, b0h[0], b0h[1]);
        mma16816(a4[1], al, b0h[2], b0h[3]);
        mma16816(a4[2], al, b1h[0], b1h[1]);
        mma16816(a4[3], al, b1h[2], b1h[3]);
    }
}

// 128x64x256 fp16 single-pass score block (R11-proven, y16 path).
__device__ __forceinline__ void score64h(uint32_t kbuf, const uint32_t ahr[16][4],
                                         uint32_t sk0, float a4[8][4]) {
    #pragma unroll
    for (int kk = 0; kk < 16; kk++) {
        const uint32_t cx = (uint32_t)(kk & 3) * 32u;
        const uint32_t bk = (uint32_t)(kk >> 2) * 8192u;
        uint32_t bh[4][4];
        #pragma unroll
        for (int t = 0; t < 4; t++)
            ldsm4(bh[t], kbuf + bk + ((sk0 + (uint32_t)t * 2048u) ^ cx));
        const uint32_t* ah = ahr[kk];
        #pragma unroll
        for (int t = 0; t < 4; t++) {
            mma16816h(a4[2 * t], ah, bh[t][0], bh[t][1]);
            mma16816h(a4[2 * t + 1], ah, bh[t][2], bh[t][3]);
        }
    }
}

// Fused: score(iter j) into aN while interleaving epilogue of iter j-1 (aP).
// 2 exp-accumulates per kk step (32 total = 8nt x 4c). ptxas interleaves the
// MUFU/FFMA stream into LDSM-scoreboard stall windows of the MMA stream.
template <bool DOEP>
__device__ __forceinline__ void score64h_ep(uint32_t kbuf, const uint32_t ahr[16][4],
                                            uint32_t sk0, float aN[8][4],
                                            const float aP[8][4],
                                            const float* wsp, const float* tsp, int lq,
                                            float& n0, float& d0, float& n1, float& d1) {
    #pragma unroll
    for (int kk = 0; kk < 16; kk++) {
        const uint32_t cx = (uint32_t)(kk & 3) * 32u;
        const uint32_t bk = (uint32_t)(kk >> 2) * 8192u;
        uint32_t bh[4][4];
        #pragma unroll
        for (int t = 0; t < 4; t++)
            ldsm4(bh[t], kbuf + bk + ((sk0 + (uint32_t)t * 2048u) ^ cx));
        if (DOEP) {
            #pragma unroll
            for (int q = 0; q < 2; q++) {
                const int f = kk * 2 + q, nt = f >> 2, c = f & 3;
                float wv = wsp[nt * 8 + lq * 2 + (c & 1)];
                float tv = tsp[nt * 8 + lq * 2 + (c & 1)];
                float e = __expf(aP[nt][c] + tv);
                if (c < 2) { d0 += e; n0 += e * wv; }
                else       { d1 += e; n1 += e * wv; }
            }
        }
        const uint32_t* ah = ahr[kk];
        #pragma unroll
        for (int t = 0; t < 4; t++) {
            mma16816h(aN[2 * t], ah, bh[t][0], bh[t][1]);
            mma16816h(aN[2 * t + 1], ah, bh[t][2], bh[t][3]);
        }
    }
}

// ---------------- kernel 0: u = Wv@Ww, p = (Wk@bq)/16, c = bv.Ww ----------------
__global__ void prep_kernel(const float* __restrict__ Wv, const float* __restrict__ Ww,
                            const float* __restrict__ bv, const float* __restrict__ Wk,
                            const float* __restrict__ bq) {
    int warp = threadIdx.x >> 5, lane = threadIdx.x & 31;
    for (int row = warp; row < HH; row += 8) {
        float su = 0.f, sp = 0.f;
        #pragma unroll
        for (int m = 0; m < 8; m++) {
            su += Wv[row * HH + m * 32 + lane] * Ww[m * 32 + lane];
            sp += Wk[row * HH + m * 32 + lane] * bq[m * 32 + lane];
        }
        for (int o = 16; o; o >>= 1) {
            su += __shfl_down_sync(0xffffffffu, su, o);
            sp += __shfl_down_sync(0xffffffffu, sp, o);
        }
        if (!lane) { g_u[row] = su; g_p[row] = sp * 0.0625f; }
    }
    if (threadIdx.x == 0) {
        float c = 0.f;
        for (int j = 0; j < HH; j++) c += bv[j] * Ww[j];
        g_c = c;
    }
}

// ---------------- kernel 1: plain bf16 hi/lo splits of Wq, Wk ----------------
__global__ void prep_w2_kernel(const float* __restrict__ Wq, const float* __restrict__ Wk) {
    int j = blockIdx.y, d = threadIdx.x;
    const float* W = blockIdx.x ? Wk : Wq;
    __nv_bfloat16* oh = blockIdx.x ? g_Wkh : g_Wqh;
    __nv_bfloat16* ol = blockIdx.x ? g_Wkl : g_Wql;
    __nv_bfloat16 hi, lo;
    split2(W[j * HH + d], hi, lo);
    oh[j * HH + d] = hi;
    ol[j * HH + d] = lo;
}

// ---------------- kernel 2: x -> fp16 + w = x.u + c, t = x.p ----------------
__global__ void xw_kernel(const float* __restrict__ x) {
    int warp = threadIdx.x >> 5, lane = threadIdx.x & 31;
    int row = blockIdx.x * 8 + warp;
    const float* xr = x + (size_t)row * HH + lane * 8;
    const float* up = g_u + lane * 8;
    const float* pp = g_p + lane * 8;
    uint32_t h16[4];
    float s = 0.f, s2 = 0.f;
    #pragma unroll
    for (int g = 0; g < 2; g++) {
        float4 v = *(const float4*)(xr + g * 4);
        h16[g * 2] = pack_h(v.x, v.y); h16[g * 2 + 1] = pack_h(v.z, v.w);
        s  += v.x * up[g * 4] + v.y * up[g * 4 + 1] + v.z * up[g * 4 + 2] + v.w * up[g * 4 + 3];
        s2 += v.x * pp[g * 4] + v.y * pp[g * 4 + 1] + v.z * pp[g * 4 + 2] + v.w * pp[g * 4 + 3];
    }
    *(uint4*)(g_x16 + (size_t)row * HH + lane * 8) = *(uint4*)h16;
    for (int o = 16; o; o >>= 1) {
        s += __shfl_down_sync(0xffffffffu, s, o);
        s2 += __shfl_down_sync(0xffffffffu, s2, o);
    }
    if (!lane) { g_w[row] = s + g_c; g_t[row] = s2; }
}

// ---------------- kernel 3: Amat = (WqWk^T)^T/16 -> fp16 ----------------
#define AM_SMEM 163840
__global__ __launch_bounds__(256, 1) void amat_mma() {
    extern __shared__ __align__(1024) char sm[];
    const uint32_t smb = smem_u32(sm);
    const int tid = threadIdx.x, warp = tid >> 5, lane = tid & 31;
    const int m0 = blockIdx.x * 128;
    const int cb = blockIdx.y * 32;

    stageA2(smb, smb + 65536u, g_Wkh + (size_t)m0 * HH, g_Wkl + (size_t)m0 * HH, tid);
    cp_commit();
    stage32(smb + 131072u, g_Wqh + (size_t)cb * HH, g_Wql + (size_t)cb * HH, tid);
    cp_commit();

    uint32_t qrowb = (uint32_t)((warp * 16 + (lane & 15)) * 128 + (lane >> 4) * 16);
    uint32_t sq = qrowb ^ ((qrowb >> 3) & 0x70);
    uint32_t kr0 = (uint32_t)((((lane & 7) + ((lane >> 4) << 3))) * 128 + ((lane & 8) << 1));
    uint32_t sk0 = kr0 ^ ((kr0 >> 3) & 0x70);
    uint32_t sk1 = sk0 + 2048u;

    cp_wait<0>(); __syncthreads();
    uint32_t ahr[16][4];
    preloadA(smb, sq, ahr);

    float acc[4][4];
    #pragma unroll
    for (int a = 0; a < 4; a++)
        #pragma unroll
        for (int b2 = 0; b2 < 4; b2++) acc[a][b2] = 0.f;
    score32(smb + 65536u, smb + 131072u, ahr, sq, sk0, sk1, acc);

    const int r0 = m0 + warp * 16 + (lane >> 2);
    #pragma unroll
    for (int nt = 0; nt < 4; nt++) {
        int col = cb + nt * 8 + (lane & 3) * 2;
        *(uint32_t*)(g_A16 + (size_t)r0 * HH + col) =
            pack_h(acc[nt][0] * 0.0625f, acc[nt][1] * 0.0625f);
        *(uint32_t*)(g_A16 + (size_t)(r0 + 8) * HH + col) =
            pack_h(acc[nt][2] * 0.0625f, acc[nt][3] * 0.0625f);
    }
}

// ---------------- kernel 4: y = x * Amat (fp16 single-pass, R13-proven) ----------------
#define Y16_SMEM 65536
__global__ __launch_bounds__(256, 1) void y16_mma() {
    extern __shared__ __align__(1024) char sm[];
    const uint32_t smb = smem_u32(sm);
    const int tid = threadIdx.x, warp = tid >> 5, lane = tid & 31;
    const int m0 = blockIdx.x * 128;

    stageY16(smb, g_x16 + (size_t)m0 * HH, tid);
    cp_commit();

    uint32_t qrowb = (uint32_t)((warp * 16 + (lane & 15)) * 128 + (lane >> 4) * 16);
    uint32_t sq = qrowb ^ ((qrowb >> 3) & 0x70);
    uint32_t kr0 = (uint32_t)((((lane & 7) + ((lane >> 4) << 3))) * 128 + ((lane & 8) << 1));
    uint32_t sk0 = kr0 ^ ((kr0 >> 3) & 0x70);

    cp_wait<0>(); __syncthreads();
    uint32_t ahr[16][4];
    preloadA(smb, sq, ahr);
    __syncthreads();   // preloads done before x area becomes B buffers

    #pragma unroll
    for (int j0 = 0; j0 < 2; j0++) {
        stage64h(smb + (uint32_t)j0 * 32768u, g_A16 + (size_t)j0 * 64 * HH, tid);
        cp_commit();
    }

    const int r0 = m0 + warp * 16 + (lane >> 2);
    for (int j = 0; j < 4; j++) {
        if (j < 3) { cp_wait<1>(); } else { cp_wait<0>(); }
        __syncthreads();
        float acc[8][4];
        #pragma unroll
        for (int a = 0; a < 8; a++)
            #pragma unroll
            for (int b2 = 0; b2 < 4; b2++) acc[a][b2] = 0.f;
        score64h(smb + (uint32_t)(j & 1) * 32768u, ahr, sk0, acc);
        __syncthreads();
        if (j + 2 < 4) {
            stage64h(smb + (uint32_t)(j & 1) * 32768u, g_A16 + (size_t)(j + 2) * 64 * HH, tid);
            cp_commit();
        }
        #pragma unroll
        for (int nt = 0; nt < 8; nt++) {
            int col = j * 64 + nt * 8 + (lane & 3) * 2;
            *(uint32_t*)(g_y16 + (size_t)r0 * HH + col) = pack_h(acc[nt][0], acc[nt][1]);
            *(uint32_t*)(g_y16 + (size_t)(r0 + 8) * HH + col) = pack_h(acc[nt][2], acc[nt][3]);
        }
    }
}

// ---------------- kernel 5: fused attention (fp16, pipelined epilogue) ----------------
// smem: [0,64K) Y16 staging -> reused as two 32K B buffers | ring @65536: 4x512B.
#define ATF_SMEM (65536 + 2048)
#define RINGF 65536u
__global__ __launch_bounds__(256, 1) void attn_f16p(const float* __restrict__ bw,
                                                    float* __restrict__ out) {
    extern __shared__ __align__(1024) char sm[];
    const uint32_t smb = smem_u32(sm);
    const int tid = threadIdx.x, warp = tid >> 5, lane = tid & 31;
    const int lq = lane & 3;
    const int b = blockIdx.y, n0 = blockIdx.x * 128;

    const __half* xp = g_x16 + (size_t)b * NN * HH;
    const float* wsrc = g_w + b * NN;
    const float* tsrc = g_t + b * NN;

    stageY16(smb, g_y16 + (size_t)(b * NN + n0) * HH, tid);
    cp_commit();

    uint32_t qrowb = (uint32_t)((warp * 16 + (lane & 15)) * 128 + (lane >> 4) * 16);
    uint32_t sq = qrowb ^ ((qrowb >> 3) & 0x70);
    uint32_t kr0 = (uint32_t)((((lane & 7) + ((lane >> 4) << 3))) * 128 + ((lane & 8) << 1));
    uint32_t sk0 = kr0 ^ ((kr0 >> 3) & 0x70);

    cp_wait<0>(); __syncthreads();
    uint32_t ahr[16][4];
    preloadA(smb, sq, ahr);
    __syncthreads();   // preloads done before the Y area is reused as B buffers

    #pragma unroll
    for (int j0 = 0; j0 < 2; j0++) {
        stage64h(smb + (uint32_t)j0 * 32768u, xp + (size_t)j0 * 64 * HH, tid);
        if (tid < 16) cp16(smb + RINGF + (uint32_t)j0 * 512u + tid * 16u,
                           wsrc + j0 * 64 + tid * 4);
        else if (tid < 32) cp16(smb + RINGF + (uint32_t)j0 * 512u + 256u + (tid - 16) * 16u,
                                tsrc + j0 * 64 + (tid - 16) * 4);
        cp_commit();
    }

    float aA[8][4], aB[8][4];
    float n0a = 0.f, d0a = 0.f, n1a = 0.f, d1a = 0.f;
    for (int j = 0; j < 32; j++) {
        if (j < 31) { cp_wait<1>(); } else { cp_wait<0>(); }
        __syncthreads();
        const uint32_t kb = smb + (uint32_t)(j & 1) * 32768u;
        const float* wsp = (const float*)(sm + RINGF + ((j + 3) & 3) * 512);  // slot (j-1)&3
        const float* tsp = wsp + 64;
        if ((j & 1) == 0) {
            #pragma unroll
            for (int a = 0; a < 8; a++)
                #pragma unroll
                for (int c = 0; c < 4; c++) aA[a][c] = 0.f;
            if (j == 0)
                score64h_ep<false>(kb, ahr, sk0, aA, aB, wsp, tsp, lq, n0a, d0a, n1a, d1a);
            else
                score64h_ep<true>(kb, ahr, sk0, aA, aB, wsp, tsp, lq, n0a, d0a, n1a, d1a);
        } else {
            #pragma unroll
            for (int a = 0; a < 8; a++)
                #pragma unroll
                for (int c = 0; c < 4; c++) aB[a][c] = 0.f;
            score64h_ep<true>(kb, ahr, sk0, aB, aA, wsp, tsp, lq, n0a, d0a, n1a, d1a);
        }
        __syncthreads();
        if (j + 2 < 32) {
            stage64h(smb + (uint32_t)(j & 1) * 32768u, xp + (size_t)(j + 2) * 64 * HH, tid);
            if (tid < 16) cp16(smb + RINGF + (uint32_t)((j + 2) & 3) * 512u + tid * 16u,
                               wsrc + (j + 2) * 64 + tid * 4);
            else if (tid < 32) cp16(smb + RINGF + (uint32_t)((j + 2) & 3) * 512u + 256u +
                                        (tid - 16) * 16u,
                                    tsrc + (j + 2) * 64 + (tid - 16) * 4);
            cp_commit();
        }
    }
    {   // final epilogue: iter 31's scores live in aB (31 odd); ring slot 31&3 = 3
        const float* wsp = (const float*)(sm + RINGF + 3 * 512);
        const float* tsp = wsp + 64;
        #pragma unroll
        for (int nt = 0; nt < 8; nt++) {
            float2 wv = *(const float2*)(wsp + nt * 8 + lq * 2);
            float2 tv = *(const float2*)(tsp + nt * 8 + lq * 2);
            float e;
            e = __expf(aB[nt][0] + tv.x); d0a += e; n0a += e * wv.x;
            e = __expf(aB[nt][1] + tv.y); d0a += e; n0a += e * wv.y;
            e = __expf(aB[nt][2] + tv.x); d1a += e; n1a += e * wv.x;
            e = __expf(aB[nt][3] + tv.y); d1a += e; n1a += e * wv.y;
        }
    }
    #pragma unroll
    for (int o = 1; o <= 2; o <<= 1) {
        n0a += __shfl_xor_sync(0xffffffffu, n0a, o);
        d0a += __shfl_xor_sync(0xffffffffu, d0a, o);
        n1a += __shfl_xor_sync(0xffffffffu, n1a, o);
        d1a += __shfl_xor_sync(0xffffffffu, d1a, o);
    }
    if (!(lane & 3)) {
        int r = n0 + warp * 16 + (lane >> 2);
        float bwv = __ldg(bw);
        out[b * NN + r] = n0a / d0a + bwv;
        out[b * NN + r + 8] = n1a / d1a + bwv;
    }
}

// ---------------- launch ----------------
extern "C" void kernel_launch(void* const* d_in, const int* in_sizes, int n_in,
                              void* d_out, int out_size) {
    const float* x  = (const float*)d_in[0];
    const float* Wq = (const float*)d_in[1];
    const float* bq = (const float*)d_in[2];
    const float* Wk = (const float*)d_in[3];
    const float* bk = (const float*)d_in[4];
    const float* Wv = (const float*)d_in[5];
    const float* bv = (const float*)d_in[6];
    const float* Ww = (const float*)d_in[7];
    const float* bw = (const float*)d_in[8];
    float* out = (float*)d_out;
    (void)bk;

    cudaFuncSetAttribute(amat_mma, cudaFuncAttributeMaxDynamicSharedMemorySize, AM_SMEM);
    cudaFuncSetAttribute(y16_mma, cudaFuncAttributeMaxDynamicSharedMemorySize, Y16_SMEM);
    cudaFuncSetAttribute(attn_f16p, cudaFuncAttributeMaxDynamicSharedMemorySize, ATF_SMEM);

    prep_kernel<<<1, 256>>>(Wv, Ww, bv, Wk, bq);
    prep_w2_kernel<<<dim3(2, 256), 256>>>(Wq, Wk);
    amat_mma<<<dim3(2, 8), 256, AM_SMEM>>>();        // Amat -> fp16
    xw_kernel<<<BB * NN / 8, 256>>>(x);              // x16, w, t
    y16_mma<<<128, 256, Y16_SMEM>>>();               // y = x * Amat (fp16)
    attn_f16p<<<dim3(16, 8), 256, ATF_SMEM>>>(bw, out);
}

// round 17
// speedup vs baseline: 1.0653x; 1.0390x over previous
#include <cuda_runtime.h>
#include <cuda_bf16.h>
#include <cuda_fp16.h>
#include <cstdint>

#define BB 8
#define NN 2048
#define HH 256

// ---------------- device scratch ----------------
__device__ __align__(16) __half       g_x16[BB*NN*HH];
__device__ __align__(16) __half       g_y16[BB*NN*HH];
__device__ __align__(16) __half       g_A16[HH*HH];   // Amat^T [col][dim], fp16
__device__ __align__(16) __nv_bfloat16 g_Wqh[HH*HH];
__device__ __align__(16) __nv_bfloat16 g_Wql[HH*HH];
__device__ __align__(16) __nv_bfloat16 g_Wkh[HH*HH];
__device__ __align__(16) __nv_bfloat16 g_Wkl[HH*HH];
__device__ __align__(16) float g_w[BB*NN];
__device__ __align__(16) float g_t[BB*NN];
__device__ __align__(16) float g_u[HH];
__device__ __align__(16) float g_p[HH];
__device__ float g_c;

// ---------------- helpers ----------------
__device__ __forceinline__ uint32_t smem_u32(const void* p) {
    return (uint32_t)__cvta_generic_to_shared(p);
}
__device__ __forceinline__ void cp16(uint32_t dst, const void* src) {
    asm volatile("cp.async.cg.shared.global [%0], [%1], 16;" :: "r"(dst), "l"(src));
}
__device__ __forceinline__ void cp_commit() { asm volatile("cp.async.commit_group;"); }
template <int N> __device__ __forceinline__ void cp_wait() {
    asm volatile("cp.async.wait_group %0;" :: "n"(N) : "memory");
}
__device__ __forceinline__ void ldsm4(uint32_t* d, uint32_t addr) {
    asm volatile("ldmatrix.sync.aligned.m8n8.x4.shared.b16 {%0,%1,%2,%3}, [%4];"
        : "=r"(d[0]), "=r"(d[1]), "=r"(d[2]), "=r"(d[3]) : "r"(addr));
}
__device__ __forceinline__ void mma16816(float* c, const uint32_t* a,
                                         uint32_t b0, uint32_t b1) {
    asm volatile("mma.sync.aligned.m16n8k16.row.col.f32.bf16.bf16.f32 "
        "{%0,%1,%2,%3}, {%4,%5,%6,%7}, {%8,%9}, {%0,%1,%2,%3};"
        : "+f"(c[0]), "+f"(c[1]), "+f"(c[2]), "+f"(c[3])
        : "r"(a[0]), "r"(a[1]), "r"(a[2]), "r"(a[3]), "r"(b0), "r"(b1));
}
__device__ __forceinline__ void mma16816h(float* c, const uint32_t* a,
                                          uint32_t b0, uint32_t b1) {
    asm volatile("mma.sync.aligned.m16n8k16.row.col.f32.f16.f16.f32 "
        "{%0,%1,%2,%3}, {%4,%5,%6,%7}, {%8,%9}, {%0,%1,%2,%3};"
        : "+f"(c[0]), "+f"(c[1]), "+f"(c[2]), "+f"(c[3])
        : "r"(a[0]), "r"(a[1]), "r"(a[2]), "r"(a[3]), "r"(b0), "r"(b1));
}
#define SW128(o) ((o) ^ (((o) >> 3) & 0x70))
__device__ __forceinline__ uint32_t pack_h(float a, float b) {
    __half2 h = __floats2half2_rn(a, b);
    return *(uint32_t*)&h;
}
__device__ __forceinline__ void split2(float v, __nv_bfloat16& h, __nv_bfloat16& l) {
    h = __float2bfloat16(v);
    l = __float2bfloat16(v - __bfloat162float(h));
}

// Stage a 32-row x 256-dim bf16 hi/lo tile (SW128, 64-dim blocks). 256 threads.
__device__ __forceinline__ void stage32(uint32_t dst, const __nv_bfloat16* ph,
                                        const __nv_bfloat16* pl, int tid) {
    #pragma unroll
    for (int i = 0; i < 4; i++) {
        int idx = tid + i * 256, r = idx >> 5, d = (idx & 31) * 8;
        uint32_t off = (uint32_t)(d >> 6) * 4096u + SW128((uint32_t)(r * 128 + (d & 63) * 2));
        cp16(dst + off, ph + (size_t)r * HH + d);
        cp16(dst + 16384u + off, pl + (size_t)r * HH + d);
    }
}
// 128-row bf16 hi/lo A tile, 256 threads (64-dim blocks stride 16384).
__device__ __forceinline__ void stageA2(uint32_t hbase, uint32_t lbase,
                                        const __nv_bfloat16* ph, const __nv_bfloat16* pl,
                                        int tid) {
    #pragma unroll
    for (int i = 0; i < 16; i++) {
        int idx = tid + i * 256, r = idx >> 5, d = (idx & 31) * 8;
        uint32_t off = (uint32_t)(d >> 6) * 16384u + SW128((uint32_t)(r * 128 + (d & 63) * 2));
        cp16(hbase + off, ph + (size_t)r * HH + d);
        cp16(lbase + off, pl + (size_t)r * HH + d);
    }
}
// 128-row x 256-dim fp16 tile at dst (64 KB, blocks stride 16384). 256 threads.
__device__ __forceinline__ void stageY16(uint32_t dst, const __half* p, int tid) {
    #pragma unroll
    for (int i = 0; i < 16; i++) {
        int idx = tid + i * 256, r = idx >> 5, d = (idx & 31) * 8;
        uint32_t off = (uint32_t)(d >> 6) * 16384u + SW128((uint32_t)(r * 128 + (d & 63) * 2));
        cp16(dst + off, p + (size_t)r * HH + d);
    }
}
// 64-row x 256-dim fp16 tile at dst (32 KB, blocks stride 8192). 256 threads.
__device__ __forceinline__ void stage64h(uint32_t dst, const __half* p, int tid) {
    #pragma unroll
    for (int i = 0; i < 8; i++) {
        int idx = tid + i * 256, r = idx >> 5, d = (idx & 31) * 8;
        uint32_t off = (uint32_t)(d >> 6) * 8192u + SW128((uint32_t)(r * 128 + (d & 63) * 2));
        cp16(dst + off, p + (size_t)r * HH + d);
    }
}
// Preload A fragments: 16 kk-steps x 4 regs (blocks stride 16384).
__device__ __forceinline__ void preloadA(uint32_t hbase, uint32_t sq, uint32_t ahr[16][4]) {
    #pragma unroll
    for (int kk = 0; kk < 16; kk++) {
        uint32_t cx = (uint32_t)(kk & 3) * 32u;
        uint32_t bq = (uint32_t)(kk >> 2) * 16384u;
        ldsm4(ahr[kk], hbase + bq + (sq ^ cx));
    }
}
// Preload TWO 16-row A-chunks (rows r0, r0+16): 16 kk x 8 regs.
__device__ __forceinline__ void preloadA2(uint32_t hbase, uint32_t sq, uint32_t ahr[16][8]) {
    #pragma unroll
    for (int kk = 0; kk < 16; kk++) {
        uint32_t cx = (uint32_t)(kk & 3) * 32u;
        uint32_t bq = (uint32_t)(kk >> 2) * 16384u;
        ldsm4(&ahr[kk][0], hbase + bq + (sq ^ cx));
        ldsm4(&ahr[kk][4], hbase + bq + (sq ^ cx) + 2048u);
    }
}

// 128x32x256 bf16 3-pass score block (Amat path, R6-proven).
__device__ __forceinline__ void score32(uint32_t albase, uint32_t kbuf,
                                        const uint32_t ahr[16][4], uint32_t sq,
                                        uint32_t sk0, uint32_t sk1, float a4[4][4]) {
    #pragma unroll
    for (int kk = 0; kk < 16; kk++) {
        const uint32_t cx = (uint32_t)(kk & 3) * 32u;
        const uint32_t bq = (uint32_t)(kk >> 2) * 16384u;
        const uint32_t bk = (uint32_t)(kk >> 2) * 4096u;
        uint32_t al[4], b0h[4], b1h[4], b0l[4], b1l[4];
        ldsm4(al, albase + bq + (sq ^ cx));
        ldsm4(b0h, kbuf + bk + (sk0 ^ cx));
        ldsm4(b1h, kbuf + bk + (sk1 ^ cx));
        ldsm4(b0l, kbuf + 16384u + bk + (sk0 ^ cx));
        ldsm4(b1l, kbuf + 16384u + bk + (sk1 ^ cx));
        const uint32_t* ah = ahr[kk];
        mma16816(a4[0], ah, b0h[0], b0h[1]);
        mma16816(a4[1], ah, b0h[2], b0h[3]);
        mma16816(a4[2], ah, b1h[0], b1h[1]);
        mma16816(a4[3], ah, b1h[2], b1h[3]);
        mma16816(a4[0], ah, b0l[0], b0l[1]);
        mma16816(a4[1], ah, b0l[2], b0l[3]);
        mma16816(a4[2], ah, b1l[0], b1l[1]);
        mma16816(a4[3], ah, b1l[2], b1l[3]);
        mma16816(a4[0], al, b0h[0], b0h[1]);
        mma16816(a4[1], al, b0h[2], b0h[3]);
        mma16816(a4[2], al, b1h[0], b1h[1]);
        mma16816(a4[3], al, b1h[2], b1h[3]);
    }
}

// 128x64x256 fp16 single-pass score block (R11-proven, y16 path).
__device__ __forceinline__ void score64h(uint32_t kbuf, const uint32_t ahr[16][4],
                                         uint32_t sk0, float a4[8][4]) {
    #pragma unroll
    for (int kk = 0; kk < 16; kk++) {
        const uint32_t cx = (uint32_t)(kk & 3) * 32u;
        const uint32_t bk = (uint32_t)(kk >> 2) * 8192u;
        uint32_t bh[4][4];
        #pragma unroll
        for (int t = 0; t < 4; t++)
            ldsm4(bh[t], kbuf + bk + ((sk0 + (uint32_t)t * 2048u) ^ cx));
        const uint32_t* ah = ahr[kk];
        #pragma unroll
        for (int t = 0; t < 4; t++) {
            mma16816h(a4[2 * t], ah, bh[t][0], bh[t][1]);
            mma16816h(a4[2 * t + 1], ah, bh[t][2], bh[t][3]);
        }
    }
}

// 32q x 32k x 256 fp16 score block: 2 A-chunks in regs, this warp's 32-key
// half of a 64-key B tile at kbuf (skh = swizzled base incl. key-half offset).
// acc[c*4 + t*2 + p][4]: c=A-chunk, t=B-ldsm (16 keys), p=n8 pair.
__device__ __forceinline__ void score32q2(uint32_t kbuf, const uint32_t ahr[16][8],
                                          uint32_t skh, float a4[8][4]) {
    #pragma unroll
    for (int kk = 0; kk < 16; kk++) {
        const uint32_t cx = (uint32_t)(kk & 3) * 32u;
        const uint32_t bk = (uint32_t)(kk >> 2) * 8192u;
        uint32_t bh[2][4];
        ldsm4(bh[0], kbuf + bk + (skh ^ cx));
        ldsm4(bh[1], kbuf + bk + ((skh + 2048u) ^ cx));
        const uint32_t* a0 = &ahr[kk][0];
        const uint32_t* a1 = &ahr[kk][4];
        mma16816h(a4[0], a0, bh[0][0], bh[0][1]);
        mma16816h(a4[1], a0, bh[0][2], bh[0][3]);
        mma16816h(a4[2], a0, bh[1][0], bh[1][1]);
        mma16816h(a4[3], a0, bh[1][2], bh[1][3]);
        mma16816h(a4[4], a1, bh[0][0], bh[0][1]);
        mma16816h(a4[5], a1, bh[0][2], bh[0][3]);
        mma16816h(a4[6], a1, bh[1][0], bh[1][1]);
        mma16816h(a4[7], a1, bh[1][2], bh[1][3]);
    }
}

// ---------------- kernel 0: u = Wv@Ww, p = (Wk@bq)/16, c = bv.Ww ----------------
__global__ void prep_kernel(const float* __restrict__ Wv, const float* __restrict__ Ww,
                            const float* __restrict__ bv, const float* __restrict__ Wk,
                            const float* __restrict__ bq) {
    int warp = threadIdx.x >> 5, lane = threadIdx.x & 31;
    for (int row = warp; row < HH; row += 8) {
        float su = 0.f, sp = 0.f;
        #pragma unroll
        for (int m = 0; m < 8; m++) {
            su += Wv[row * HH + m * 32 + lane] * Ww[m * 32 + lane];
            sp += Wk[row * HH + m * 32 + lane] * bq[m * 32 + lane];
        }
        for (int o = 16; o; o >>= 1) {
            su += __shfl_down_sync(0xffffffffu, su, o);
            sp += __shfl_down_sync(0xffffffffu, sp, o);
        }
        if (!lane) { g_u[row] = su; g_p[row] = sp * 0.0625f; }
    }
    if (threadIdx.x == 0) {
        float c = 0.f;
        for (int j = 0; j < HH; j++) c += bv[j] * Ww[j];
        g_c = c;
    }
}

// ---------------- kernel 1: plain bf16 hi/lo splits of Wq, Wk ----------------
__global__ void prep_w2_kernel(const float* __restrict__ Wq, const float* __restrict__ Wk) {
    int j = blockIdx.y, d = threadIdx.x;
    const float* W = blockIdx.x ? Wk : Wq;
    __nv_bfloat16* oh = blockIdx.x ? g_Wkh : g_Wqh;
    __nv_bfloat16* ol = blockIdx.x ? g_Wkl : g_Wql;
    __nv_bfloat16 hi, lo;
    split2(W[j * HH + d], hi, lo);
    oh[j * HH + d] = hi;
    ol[j * HH + d] = lo;
}

// ---------------- kernel 2: x -> fp16 + w = x.u + c, t = x.p ----------------
__global__ void xw_kernel(const float* __restrict__ x) {
    int warp = threadIdx.x >> 5, lane = threadIdx.x & 31;
    int row = blockIdx.x * 8 + warp;
    const float* xr = x + (size_t)row * HH + lane * 8;
    const float* up = g_u + lane * 8;
    const float* pp = g_p + lane * 8;
    uint32_t h16[4];
    float s = 0.f, s2 = 0.f;
    #pragma unroll
    for (int g = 0; g < 2; g++) {
        float4 v = *(const float4*)(xr + g * 4);
        h16[g * 2] = pack_h(v.x, v.y); h16[g * 2 + 1] = pack_h(v.z, v.w);
        s  += v.x * up[g * 4] + v.y * up[g * 4 + 1] + v.z * up[g * 4 + 2] + v.w * up[g * 4 + 3];
        s2 += v.x * pp[g * 4] + v.y * pp[g * 4 + 1] + v.z * pp[g * 4 + 2] + v.w * pp[g * 4 + 3];
    }
    *(uint4*)(g_x16 + (size_t)row * HH + lane * 8) = *(uint4*)h16;
    for (int o = 16; o; o >>= 1) {
        s += __shfl_down_sync(0xffffffffu, s, o);
        s2 += __shfl_down_sync(0xffffffffu, s2, o);
    }
    if (!lane) { g_w[row] = s + g_c; g_t[row] = s2; }
}

// ---------------- kernel 3: Amat = (WqWk^T)^T/16 -> fp16 ----------------
#define AM_SMEM 163840
__global__ __launch_bounds__(256, 1) void amat_mma() {
    extern __shared__ __align__(1024) char sm[];
    const uint32_t smb = smem_u32(sm);
    const int tid = threadIdx.x, warp = tid >> 5, lane = tid & 31;
    const int m0 = blockIdx.x * 128;
    const int cb = blockIdx.y * 32;

    stageA2(smb, smb + 65536u, g_Wkh + (size_t)m0 * HH, g_Wkl + (size_t)m0 * HH, tid);
    cp_commit();
    stage32(smb + 131072u, g_Wqh + (size_t)cb * HH, g_Wql + (size_t)cb * HH, tid);
    cp_commit();

    uint32_t qrowb = (uint32_t)((warp * 16 + (lane & 15)) * 128 + (lane >> 4) * 16);
    uint32_t sq = qrowb ^ ((qrowb >> 3) & 0x70);
    uint32_t kr0 = (uint32_t)((((lane & 7) + ((lane >> 4) << 3))) * 128 + ((lane & 8) << 1));
    uint32_t sk0 = kr0 ^ ((kr0 >> 3) & 0x70);
    uint32_t sk1 = sk0 + 2048u;

    cp_wait<0>(); __syncthreads();
    uint32_t ahr[16][4];
    preloadA(smb, sq, ahr);

    float acc[4][4];
    #pragma unroll
    for (int a = 0; a < 4; a++)
        #pragma unroll
        for (int b2 = 0; b2 < 4; b2++) acc[a][b2] = 0.f;
    score32(smb + 65536u, smb + 131072u, ahr, sq, sk0, sk1, acc);

    const int r0 = m0 + warp * 16 + (lane >> 2);
    #pragma unroll
    for (int nt = 0; nt < 4; nt++) {
        int col = cb + nt * 8 + (lane & 3) * 2;
        *(uint32_t*)(g_A16 + (size_t)r0 * HH + col) =
            pack_h(acc[nt][0] * 0.0625f, acc[nt][1] * 0.0625f);
        *(uint32_t*)(g_A16 + (size_t)(r0 + 8) * HH + col) =
            pack_h(acc[nt][2] * 0.0625f, acc[nt][3] * 0.0625f);
    }
}

// ---------------- kernel 4: y = x * Amat (fp16 single-pass, R13-proven) ----------------
#define Y16_SMEM 65536
__global__ __launch_bounds__(256, 1) void y16_mma() {
    extern __shared__ __align__(1024) char sm[];
    const uint32_t smb = smem_u32(sm);
    const int tid = threadIdx.x, warp = tid >> 5, lane = tid & 31;
    const int m0 = blockIdx.x * 128;

    stageY16(smb, g_x16 + (size_t)m0 * HH, tid);
    cp_commit();

    uint32_t qrowb = (uint32_t)((warp * 16 + (lane & 15)) * 128 + (lane >> 4) * 16);
    uint32_t sq = qrowb ^ ((qrowb >> 3) & 0x70);
    uint32_t kr0 = (uint32_t)((((lane & 7) + ((lane >> 4) << 3))) * 128 + ((lane & 8) << 1));
    uint32_t sk0 = kr0 ^ ((kr0 >> 3) & 0x70);

    cp_wait<0>(); __syncthreads();
    uint32_t ahr[16][4];
    preloadA(smb, sq, ahr);
    __syncthreads();   // preloads done before x area becomes B buffers

    #pragma unroll
    for (int j0 = 0; j0 < 2; j0++) {
        stage64h(smb + (uint32_t)j0 * 32768u, g_A16 + (size_t)j0 * 64 * HH, tid);
        cp_commit();
    }

    const int r0 = m0 + warp * 16 + (lane >> 2);
    for (int j = 0; j < 4; j++) {
        if (j < 3) { cp_wait<1>(); } else { cp_wait<0>(); }
        __syncthreads();
        float acc[8][4];
        #pragma unroll
        for (int a = 0; a < 8; a++)
            #pragma unroll
            for (int b2 = 0; b2 < 4; b2++) acc[a][b2] = 0.f;
        score64h(smb + (uint32_t)(j & 1) * 32768u, ahr, sk0, acc);
        __syncthreads();
        if (j + 2 < 4) {
            stage64h(smb + (uint32_t)(j & 1) * 32768u, g_A16 + (size_t)(j + 2) * 64 * HH, tid);
            cp_commit();
        }
        #pragma unroll
        for (int nt = 0; nt < 8; nt++) {
            int col = j * 64 + nt * 8 + (lane & 3) * 2;
            *(uint32_t*)(g_y16 + (size_t)r0 * HH + col) = pack_h(acc[nt][0], acc[nt][1]);
            *(uint32_t*)(g_y16 + (size_t)(r0 + 8) * HH + col) = pack_h(acc[nt][2], acc[nt][3]);
        }
    }
}

// ---------------- kernel 5: fused attention (2-D warp split: 4q x 2k) ----------------
// 8 warps: wq = warp&3 (32 q-rows in regs), kh = warp>>2 (32-key half).
// smem: [0,64K) Y16 staging -> reused as two 32K B buffers | ring @65536: 4x512B
//       | scratch @67584: 2 x 128 x float2 = 2KB. Total 69632.
#define ATQ_SMEM 69632
#define RINGQ 65536u
#define SCRQ 67584u
__global__ __launch_bounds__(256, 1) void attn_f16q(const float* __restrict__ bw,
                                                    float* __restrict__ out) {
    extern __shared__ __align__(1024) char sm[];
    const uint32_t smb = smem_u32(sm);
    const int tid = threadIdx.x, warp = tid >> 5, lane = tid & 31;
    const int wq = warp & 3, kh = warp >> 2;
    const int lq = lane & 3;
    const int b = blockIdx.y, n0 = blockIdx.x * 128;

    const __half* xp = g_x16 + (size_t)b * NN * HH;
    const float* wsrc = g_w + b * NN;
    const float* tsrc = g_t + b * NN;

    stageY16(smb, g_y16 + (size_t)(b * NN + n0) * HH, tid);
    cp_commit();

    // A base: rows wq*32 + (lane&15); chunk1 at +16 rows (+2048B).
    uint32_t qrowb = (uint32_t)((wq * 32 + (lane & 15)) * 128 + (lane >> 4) * 16);
    uint32_t sq = qrowb ^ ((qrowb >> 3) & 0x70);
    // B base: key rows of this warp's half: +kh*32 rows (+4096B).
    uint32_t kr0 = (uint32_t)((((lane & 7) + ((lane >> 4) << 3))) * 128 + ((lane & 8) << 1));
    uint32_t skh = (kr0 ^ ((kr0 >> 3) & 0x70)) + (uint32_t)kh * 4096u;

    cp_wait<0>(); __syncthreads();
    uint32_t ahr[16][8];
    preloadA2(smb, sq, ahr);
    __syncthreads();   // preloads done before the Y area is reused as B buffers

    #pragma unroll
    for (int j0 = 0; j0 < 2; j0++) {
        stage64h(smb + (uint32_t)j0 * 32768u, xp + (size_t)j0 * 64 * HH, tid);
        if (tid < 16) cp16(smb + RINGQ + (uint32_t)j0 * 512u + tid * 16u,
                           wsrc + j0 * 64 + tid * 4);
        else if (tid < 32) cp16(smb + RINGQ + (uint32_t)j0 * 512u + 256u + (tid - 16) * 16u,
                                tsrc + j0 * 64 + (tid - 16) * 4);
        cp_commit();
    }

    // num/den: [A-chunk c][row-in-frag 0/8]
    float num[2][2] = {{0.f, 0.f}, {0.f, 0.f}};
    float den[2][2] = {{0.f, 0.f}, {0.f, 0.f}};
    for (int j = 0; j < 32; j++) {
        if (j < 31) { cp_wait<1>(); } else { cp_wait<0>(); }
        __syncthreads();
        float acc[8][4];
        #pragma unroll
        for (int a = 0; a < 8; a++)
            #pragma unroll
            for (int c = 0; c < 4; c++) acc[a][c] = 0.f;
        score32q2(smb + (uint32_t)(j & 1) * 32768u, ahr, skh, acc);
        __syncthreads();
        if (j + 2 < 32) {
            stage64h(smb + (uint32_t)(j & 1) * 32768u, xp + (size_t)(j + 2) * 64 * HH, tid);
            if (tid < 16) cp16(smb + RINGQ + (uint32_t)((j + 2) & 3) * 512u + tid * 16u,
                               wsrc + (j + 2) * 64 + tid * 4);
            else if (tid < 32) cp16(smb + RINGQ + (uint32_t)((j + 2) & 3) * 512u + 256u +
                                        (tid - 16) * 16u,
                                    tsrc + (j + 2) * 64 + (tid - 16) * 4);
            cp_commit();
        }
        const float* wsp = (const float*)(sm + RINGQ + (j & 3) * 512) + kh * 32;
        const float* tsp = wsp + 64;   // t-array mirrors w at +64 floats
        #pragma unroll
        for (int c = 0; c < 2; c++) {
            #pragma unroll
            for (int t = 0; t < 2; t++) {
                #pragma unroll
                for (int p = 0; p < 2; p++) {
                    const int a = c * 4 + t * 2 + p;
                    const int kb2 = t * 16 + p * 8 + lq * 2;
                    float2 wv = *(const float2*)(wsp + kb2);
                    float2 tv = *(const float2*)(tsp + kb2);
                    float e0 = __expf(acc[a][0] + tv.x);
                    float e1 = __expf(acc[a][1] + tv.y);
                    float e2 = __expf(acc[a][2] + tv.x);
                    float e3 = __expf(acc[a][3] + tv.y);
                    den[c][0] += e0 + e1; num[c][0] += e0 * wv.x + e1 * wv.y;
                    den[c][1] += e2 + e3; num[c][1] += e2 * wv.x + e3 * wv.y;
                }
            }
        }
    }
    // lane-quad reduce (lanes sharing a q-row)
    #pragma unroll
    for (int c = 0; c < 2; c++)
        #pragma unroll
        for (int r = 0; r < 2; r++)
            #pragma unroll
            for (int o = 1; o <= 2; o <<= 1) {
                num[c][r] += __shfl_xor_sync(0xffffffffu, num[c][r], o);
                den[c][r] += __shfl_xor_sync(0xffffffffu, den[c][r], o);
            }
    // cross-key-half combine via scratch
    if (!(lane & 3)) {
        #pragma unroll
        for (int c = 0; c < 2; c++) {
            int r0 = wq * 32 + c * 16 + (lane >> 2);
            *(float2*)(sm + SCRQ + (uint32_t)kh * 1024u + (uint32_t)r0 * 8u) =
                make_float2(num[c][0], den[c][0]);
            *(float2*)(sm + SCRQ + (uint32_t)kh * 1024u + (uint32_t)(r0 + 8) * 8u) =
                make_float2(num[c][1], den[c][1]);
        }
    }
    __syncthreads();
    if (tid < 128) {
        float2 a = *(const float2*)(sm + SCRQ + (uint32_t)tid * 8u);
        float2 b2 = *(const float2*)(sm + SCRQ + 1024u + (uint32_t)tid * 8u);
        out[b * NN + n0 + tid] = (a.x + b2.x) / (a.y + b2.y) + __ldg(bw);
    }
}

// ---------------- launch ----------------
extern "C" void kernel_launch(void* const* d_in, const int* in_sizes, int n_in,
                              void* d_out, int out_size) {
    const float* x  = (const float*)d_in[0];
    const float* Wq = (const float*)d_in[1];
    const float* bq = (const float*)d_in[2];
    const float* Wk = (const float*)d_in[3];
    const float* bk = (const float*)d_in[4];
    const float* Wv = (const float*)d_in[5];
    const float* bv = (const float*)d_in[6];
    const float* Ww = (const float*)d_in[7];
    const float* bw = (const float*)d_in[8];
    float* out = (float*)d_out;
    (void)bk;

    cudaFuncSetAttribute(amat_mma, cudaFuncAttributeMaxDynamicSharedMemorySize, AM_SMEM);
    cudaFuncSetAttribute(y16_mma, cudaFuncAttributeMaxDynamicSharedMemorySize, Y16_SMEM);
    cudaFuncSetAttribute(attn_f16q, cudaFuncAttributeMaxDynamicSharedMemorySize, ATQ_SMEM);

    prep_kernel<<<1, 256>>>(Wv, Ww, bv, Wk, bq);
    prep_w2_kernel<<<dim3(2, 256), 256>>>(Wq, Wk);
    amat_mma<<<dim3(2, 8), 256, AM_SMEM>>>();        // Amat -> fp16
    xw_kernel<<<BB * NN / 8, 256>>>(x);              // x16, w, t
    y16_mma<<<128, 256, Y16_SMEM>>>();               // y = x * Amat (fp16)
    attn_f16q<<<dim3(16, 8), 256, ATQ_SMEM>>>(bw, out);
}